// round 16
// baseline (speedup 1.0000x reference)
#include <cuda_runtime.h>
#include <cuda_fp16.h>
#include <cstdint>

#define B_SZ    16
#define C_IN    64
#define N_POS   40962
#define C_OUT   32
#define K_CH    224                 // 7*C_OUT, permuted: k = sub*32 + o
#define NEW_N   (4*N_POS - 6)       // 163842
#define TILE_P  64
#define TILES_PER_B 641             // gemm tiles per batch
#define GM      128
#define GBLK_PER_B 1281             // ceil(163842/128) gather blocks per batch
#define SEG     (TILES_PER_B + GBLK_PER_B)   // 1922
#define TOTAL_ITEMS (641 + 15*SEG + GBLK_PER_B)  // 30752
#define GRID    296
#define NTHR    256

// 293 MB scratch for y' [B][N][224] fp16 (permuted channel layout)
__device__ __half g_y[(size_t)B_SZ * N_POS * K_CH];

// [0]=queue head, [1+b]=tiles-done counter for batch b. Reset via memset.
__device__ unsigned g_sync[1 + B_SZ];

// ---------------------------------------------------------------------------
// smem (dynamic, bytes). gemm uses XH/WH/ASF/STAGE; gather aliases smx onto
// the ASF+STAGE region (items are serialized within a CTA by barriers).
// 83 KB -> 2 CTAs/SM.
// ---------------------------------------------------------------------------
#define SM_XH    0        // xh [64][64] fp16 : 8192 (SW128)
#define SM_WH    8192     // wh [224][64] fp16 : 28672 (SW128) - persistent
#define SM_ASF   36864    // x staging f32 [64][64] : 16384  | smx[128][33]: 16896
#define SM_STAGE 53248    // epilogue stage fp16 [64][232] : 29696
#define STG_ROW_H 232
#define SM_TOTAL 82944

static __device__ __forceinline__ uint32_t smem_u32(const void* p) {
    uint32_t a;
    asm("{ .reg .u64 t; cvta.to.shared.u64 t, %1; cvt.u32.u64 %0, t; }" : "=r"(a) : "l"(p));
    return a;
}
static __device__ __forceinline__ uint32_t swz(uint32_t off) {
    return off ^ ((off >> 3) & 0x70);
}
static __device__ __forceinline__ void ldsm_x4(uint32_t* a, uint32_t addr) {
    asm volatile("ldmatrix.sync.aligned.m8n8.x4.shared.b16 {%0,%1,%2,%3}, [%4];"
                 : "=r"(a[0]), "=r"(a[1]), "=r"(a[2]), "=r"(a[3]) : "r"(addr));
}
static __device__ __forceinline__ void ldsm_x2(uint32_t* b, uint32_t addr) {
    asm volatile("ldmatrix.sync.aligned.m8n8.x2.shared.b16 {%0,%1}, [%2];"
                 : "=r"(b[0]), "=r"(b[1]) : "r"(addr));
}
static __device__ __forceinline__ void mma_f16(float* d, const uint32_t* a, const uint32_t* b) {
    asm volatile("mma.sync.aligned.m16n8k16.row.col.f32.f16.f16.f32 "
                 "{%0,%1,%2,%3}, {%4,%5,%6,%7}, {%8,%9}, {%0,%1,%2,%3};"
                 : "+f"(d[0]), "+f"(d[1]), "+f"(d[2]), "+f"(d[3])
                 : "r"(a[0]), "r"(a[1]), "r"(a[2]), "r"(a[3]), "r"(b[0]), "r"(b[1]));
}

// ---------------------------------------------------------------------------
// Unified work-queue kernel: 30752 items.
//  item order: gemm(0)[641] | {gemm(s+1)[641], gather(s)[1281]} s=0..14 |
//              gather(15)[1281]
//  -> all gemm(b) dequeued before any gather(b); deadlock-free spin.
// ---------------------------------------------------------------------------
__global__ void __launch_bounds__(NTHR, 2)
fused_queue_kernel(const float* __restrict__ x,
                   const float* __restrict__ W,
                   const float* __restrict__ bias,
                   const int*   __restrict__ top,
                   const int*   __restrict__ down,
                   float*       __restrict__ out)
{
    extern __shared__ char sm[];
    __shared__ unsigned s_item;
    const uint32_t smb = smem_u32(sm);
    float*  Asf = (float*)(sm + SM_ASF);
    __half* stg = (__half*)(sm + SM_STAGE);
    float (*smx)[33] = (float(*)[33])(sm + SM_ASF);   // gather transpose

    const int tid = threadIdx.x;
    const int w   = tid >> 5;
    const int l   = tid & 31;
    // gemm mapping
    const int wm  = w & 1;           // 32-row group
    const int wn  = w >> 1;          // 56-col group
    // gather mapping
    const int g8  = l >> 2;          // m within octet
    const int l4  = l & 3;           // uint4 slot

    // --- one-time: build wh (permuted, fp16, swizzled) ---
    for (int idx = tid; idx < K_CH * C_IN; idx += NTHR) {
        int n = idx >> 6, c = idx & 63;
        int rw = (n & 31) * 7 + (n >> 5);
        uint32_t off = swz((uint32_t)(n * 128 + c * 2));
        *(__half*)(sm + SM_WH + off) = __float2half_rn(W[rw * C_IN + c]);
    }

    // --- gemm per-thread bias regs ---
    float2 bb[7];
    {
        int nbase = wn * 56 + (l & 3) * 2;
        #pragma unroll
        for (int nt = 0; nt < 7; nt++) {
            int n0 = nbase + nt * 8;
            int n1 = n0 + 1;
            bb[nt].x = bias[(n0 & 31) * 7 + (n0 >> 5)];
            bb[nt].y = bias[(n1 & 31) * 7 + (n1 >> 5)];
        }
    }
    const uint32_t a_lane = (uint32_t)((wm * 32 + (l & 15)) * 128 + (l >> 4) * 16);
    const uint32_t b_lane = (uint32_t)((wn * 56 + (l & 7)) * 128 + ((l >> 3) & 1) * 16);
    const int cp  = tid & 63;
    const int cc0 = (tid >> 6) * 16;

    __syncthreads();

    for (;;) {
        if (tid == 0) s_item = atomicAdd(&g_sync[0], 1u);
        __syncthreads();
        const unsigned i = s_item;
        if (i >= (unsigned)TOTAL_ITEMS) break;

        // --- decode item ---
        int type, b, t;
        if (i < 641u) { type = 0; b = 0; t = (int)i; }
        else {
            unsigned j = i - 641u;
            if (j < 15u * SEG) {
                unsigned s = j / SEG, k = j - s * SEG;
                if (k < 641u) { type = 0; b = (int)s + 1; t = (int)k; }
                else          { type = 1; b = (int)s;     t = (int)(k - 641u); }
            } else { type = 1; b = 15; t = (int)(j - 15u * SEG); }
        }

        if (type == 0) {
            // ================= GEMM tile (b, t) =================
            const int p0 = t * TILE_P;
            const float* xb = x + (size_t)b * C_IN * N_POS;
            __half* yb = g_y + (size_t)b * N_POS * K_CH;

            // stage Asf[c][p]
            #pragma unroll
            for (int it2 = 0; it2 < 16; it2++) {
                int idx = it2 * NTHR + tid;
                int c = idx >> 6, p = idx & 63;
                Asf[idx] = (p0 + p < N_POS) ? xb[(size_t)c * N_POS + p0 + p] : 0.0f;
            }
            __syncthreads();

            // convert -> xh fp16 swizzled
            #pragma unroll
            for (int blk = 0; blk < 2; blk++) {
                int cb = cc0 + blk * 8;
                float xv[8];
                #pragma unroll
                for (int j2 = 0; j2 < 8; j2++) xv[j2] = Asf[(cb + j2) * TILE_P + cp];
                uint32_t hi[4];
                #pragma unroll
                for (int q = 0; q < 4; q++) {
                    half2 h = __floats2half2_rn(xv[2 * q], xv[2 * q + 1]);
                    hi[q] = *(uint32_t*)&h;
                }
                uint32_t off = swz((uint32_t)(cp * 128 + cb * 2));
                *(uint4*)(sm + SM_XH + off) = make_uint4(hi[0], hi[1], hi[2], hi[3]);
            }
            __syncthreads();

            // MMA: 4 k16-chunks
            float d[2][7][4];
            #pragma unroll
            for (int mt = 0; mt < 2; mt++)
                #pragma unroll
                for (int nt = 0; nt < 7; nt++)
                    #pragma unroll
                    for (int q = 0; q < 4; q++) d[mt][nt][q] = 0.0f;

            #pragma unroll
            for (int kci = 0; kci < 4; kci++) {
                const uint32_t kcb = kci * 32;
                uint32_t bfr[7][2];
                #pragma unroll
                for (int nt = 0; nt < 7; nt++)
                    ldsm_x2(bfr[nt], smb + SM_WH + swz(b_lane + (uint32_t)nt * 1024 + kcb));
                uint32_t ah[2][4];
                ldsm_x4(ah[0], smb + SM_XH + swz(a_lane + kcb));
                ldsm_x4(ah[1], smb + SM_XH + swz(a_lane + 2048 + kcb));
                #pragma unroll
                for (int nt = 0; nt < 7; nt++) {
                    mma_f16(d[0][nt], ah[0], bfr[nt]);
                    mma_f16(d[1][nt], ah[1], bfr[nt]);
                }
            }

            // epilogue stage: bias + fp16 -> smem
            {
                const int qrow = l >> 2;
                const int ncol = wn * 56 + (l & 3) * 2;
                #pragma unroll
                for (int mt = 0; mt < 2; mt++) {
                    #pragma unroll
                    for (int rsel = 0; rsel < 2; rsel++) {
                        int row = wm * 32 + mt * 16 + rsel * 8 + qrow;
                        __half* sr = stg + row * STG_ROW_H + ncol;
                        #pragma unroll
                        for (int nt = 0; nt < 7; nt++) {
                            float vx = d[mt][nt][rsel * 2 + 0] + bb[nt].x;
                            float vy = d[mt][nt][rsel * 2 + 1] + bb[nt].y;
                            *(half2*)(sr + nt * 8) = __floats2half2_rn(vx, vy);
                        }
                    }
                }
            }
            __syncthreads();

            // coalesced writeback: warp w -> rows w*8..+7 (448B rows)
            if (l < 28) {
                #pragma unroll
                for (int r = 0; r < 8; r++) {
                    int row = w * 8 + r;
                    int gp = p0 + row;
                    if (gp < N_POS) {
                        uint4 v = *(const uint4*)(stg + row * STG_ROW_H + l * 8);
                        *(uint4*)(yb + (size_t)gp * K_CH + l * 8) = v;
                    }
                }
            }
            __syncthreads();

            // release: tile done
            if (tid == 0) {
                __threadfence();
                atomicAdd(&g_sync[1 + b], 1u);
            }
        } else {
            // ================= gather block (b, t) =================
            const int m0 = t * GM;
            // acquire: wait for all tiles of batch b
            if (tid == 0) {
                while (atomicAdd(&g_sync[1 + b], 0u) < (unsigned)TILES_PER_B)
                    __nanosleep(128);
                __threadfence();
            }
            __syncthreads();

            const __half* yb = g_y + (size_t)b * N_POS * K_CH;

            // phase 1: index loads (2 octets/thread)
            int jx[2], jy[2];
            #pragma unroll
            for (int i2 = 0; i2 < 2; i2++) {
                int m = m0 + w * 16 + i2 * 8 + g8;
                jx[i2] = -1; jy[i2] = -1;
                if (m < NEW_N) {
                    if (m < N_POS) {
                        jx[i2] = __ldg(top + m);
                    } else {
                        int2 jj = *(const int2*)(down + 2 * (m - N_POS));
                        jx[i2] = jj.x; jy[i2] = jj.y;
                    }
                }
            }

            // phase 2: value loads (up to 4 uint4 in flight)
            uint4 v0[2], v1[2];
            #pragma unroll
            for (int i2 = 0; i2 < 2; i2++) {
                v0[i2] = make_uint4(0u, 0u, 0u, 0u);
                if (jx[i2] >= 0) {
                    int s = jx[i2] / N_POS, p = jx[i2] - s * N_POS;
                    v0[i2] = *(const uint4*)(yb + (size_t)p * K_CH + s * 32 + l4 * 8);
                }
            }
            #pragma unroll
            for (int i2 = 0; i2 < 2; i2++) {
                if (jy[i2] >= 0) {
                    int s = jy[i2] / N_POS, p = jy[i2] - s * N_POS;
                    v1[i2] = *(const uint4*)(yb + (size_t)p * K_CH + s * 32 + l4 * 8);
                }
            }

            // phase 3: convert + STS transpose
            #pragma unroll
            for (int i2 = 0; i2 < 2; i2++) {
                int mm = w * 16 + i2 * 8 + g8;
                float vf[8];
                const half2* h0 = (const half2*)&v0[i2];
                #pragma unroll
                for (int q = 0; q < 4; q++) {
                    float2 f = __half22float2(h0[q]);
                    vf[2 * q] = f.x; vf[2 * q + 1] = f.y;
                }
                if (jy[i2] >= 0) {
                    const half2* h1 = (const half2*)&v1[i2];
                    #pragma unroll
                    for (int q = 0; q < 4; q++) {
                        float2 f = __half22float2(h1[q]);
                        vf[2 * q]     = 0.5f * (vf[2 * q] + f.x);
                        vf[2 * q + 1] = 0.5f * (vf[2 * q + 1] + f.y);
                    }
                }
                float* s = &smx[mm][l4 * 8];
                #pragma unroll
                for (int j2 = 0; j2 < 8; j2++) s[j2] = vf[j2];
            }
            __syncthreads();

            // transpose write: out[b][o][m], float2 along m
            float* ob = out + (size_t)b * C_OUT * NEW_N;
            #pragma unroll
            for (int it2 = 0; it2 < C_OUT * (GM / 2) / NTHR; it2++) {   // 8
                int idx = it2 * NTHR + tid;
                int o = idx >> 6;
                int q = idx & 63;
                int m = m0 + 2 * q;
                if (m < NEW_N) {
                    float2 v = make_float2(smx[2 * q][o], smx[2 * q + 1][o]);
                    *(float2*)(ob + (size_t)o * NEW_N + m) = v;
                }
            }
            __syncthreads();   // smx reuse + s_item safety
        }
    }
}

// ---------------------------------------------------------------------------
extern "C" void kernel_launch(void* const* d_in, const int* in_sizes, int n_in,
                              void* d_out, int out_size)
{
    const float* x    = (const float*)d_in[0];
    const float* W    = (const float*)d_in[1];
    const float* bias = (const float*)d_in[2];
    const int*   top  = (const int*)d_in[3];
    const int*   down = (const int*)d_in[4];
    float* out = (float*)d_out;

    static void* sync_addr = nullptr;
    if (!sync_addr) {
        cudaGetSymbolAddress(&sync_addr, g_sync);
        cudaFuncSetAttribute(fused_queue_kernel,
                             cudaFuncAttributeMaxDynamicSharedMemorySize, SM_TOTAL);
    }

    // reset queue + done counters (graph-capturable async memset)
    cudaMemsetAsync(sync_addr, 0, sizeof(unsigned) * (1 + B_SZ));

    fused_queue_kernel<<<GRID, NTHR, SM_TOTAL>>>(x, W, bias, top, down, out);
}